// round 3
// baseline (speedup 1.0000x reference)
#include <cuda_runtime.h>
#include <cstdint>
#include <cstddef>

#define BATCH  8192
#define DIN    784
#define HID    1200
#define DOUT   10
#define TSTEPS 35

// ---------------- device state (no allocs allowed) ----------------
__device__ float g_spk [(size_t)BATCH * DIN];
__device__ float g_mem1[(size_t)BATCH * HID];
__device__ float g_sum1[(size_t)BATCH * HID];
__device__ float g_mem2[(size_t)BATCH * HID];
__device__ float g_sum2[(size_t)BATCH * HID];
__device__ float g_mem3[(size_t)BATCH * DOUT];
__device__ float g_sum3[(size_t)BATCH * DOUT];

// ---------------- Threefry-2x32 (20 rounds), exact JAX semantics ----------------
__host__ __device__ __forceinline__ uint32_t rotl32(uint32_t v, int r) {
#ifdef __CUDA_ARCH__
    return __funnelshift_l(v, v, r);
#else
    return (v << r) | (v >> (32 - r));
#endif
}

__host__ __device__ __forceinline__ void threefry2x32(
    uint32_t k0, uint32_t k1, uint32_t x0, uint32_t x1,
    uint32_t& o0, uint32_t& o1)
{
    uint32_t ks2 = k0 ^ k1 ^ 0x1BD11BDAu;
    x0 += k0; x1 += k1;
#define TF_R(r) { x0 += x1; x1 = rotl32(x1, (r)); x1 ^= x0; }
    TF_R(13) TF_R(15) TF_R(26) TF_R(6)
    x0 += k1;  x1 += ks2 + 1u;
    TF_R(17) TF_R(29) TF_R(16) TF_R(24)
    x0 += ks2; x1 += k0 + 2u;
    TF_R(13) TF_R(15) TF_R(26) TF_R(6)
    x0 += k0;  x1 += k1 + 3u;
    TF_R(17) TF_R(29) TF_R(16) TF_R(24)
    x0 += k1;  x1 += ks2 + 4u;
    TF_R(13) TF_R(15) TF_R(26) TF_R(6)
    x0 += ks2; x1 += k0 + 5u;
#undef TF_R
    o0 = x0; o1 = x1;
}

// ---------------- kernels ----------------
__global__ void zero_state_kernel() {
    size_t i = (size_t)blockIdx.x * blockDim.x + threadIdx.x;
    size_t stride = (size_t)gridDim.x * blockDim.x;
    size_t total = (size_t)BATCH * HID;
    for (size_t p = i; p < total; p += stride) {
        g_mem1[p] = 0.f; g_sum1[p] = 0.f;
        g_mem2[p] = 0.f; g_sum2[p] = 0.f;
    }
    if (i < (size_t)BATCH * DOUT) { g_mem3[i] = 0.f; g_sum3[i] = 0.f; }
}

// JAX threefry_partitionable random bits (bit_width=32):
//   counter = (i >> 32, i & 0xffffffff) = (0, i)
//   bits    = out0 ^ out1           <-- XOR of BOTH output words (prng.py)
__global__ void spike_gen_kernel(const float* __restrict__ x, uint32_t kt0, uint32_t kt1) {
    int i = blockIdx.x * blockDim.x + threadIdx.x;
    if (i >= BATCH * DIN) return;
    uint32_t y0, y1;
    threefry2x32(kt0, kt1, 0u, (uint32_t)i, y0, y1);
    uint32_t bits = y0 ^ y1;
    uint32_t fb = (bits >> 9) | 0x3f800000u;
    float u = __uint_as_float(fb) - 1.0f;
    g_spk[i] = (u * 5.0f <= x[i]) ? 1.0f : 0.0f;
}

// Fused C = A(8192 x K) @ W(N x K)^T  ; then LIF update on (mem, spksum).
// Tiles 128x128x16, 256 threads, 8x8 per thread.
__global__ __launch_bounds__(256, 1) void gemm_lif_kernel(
    const float* __restrict__ A, const float* __restrict__ W,
    float* __restrict__ mem, float* __restrict__ spksum,
    int N, int K)
{
    __shared__ float As[16][132];
    __shared__ float Bs[16][132];

    const int tid  = threadIdx.x;
    const int row0 = blockIdx.y * 128;
    const int col0 = blockIdx.x * 128;
    const int lr = tid >> 2;          // 0..63
    const int lk = (tid & 3) << 2;    // 0,4,8,12
    const int ty = tid >> 4;          // 0..15
    const int tx = tid & 15;          // 0..15

    float acc[8][8];
#pragma unroll
    for (int i = 0; i < 8; i++)
#pragma unroll
        for (int j = 0; j < 8; j++) acc[i][j] = 0.f;

    for (int k0 = 0; k0 < K; k0 += 16) {
#pragma unroll
        for (int h = 0; h < 2; h++) {
            int r = lr + (h << 6);
            float4 va = *reinterpret_cast<const float4*>(
                A + (size_t)(row0 + r) * K + (k0 + lk));
            As[lk + 0][r] = va.x; As[lk + 1][r] = va.y;
            As[lk + 2][r] = va.z; As[lk + 3][r] = va.w;
            int gn = col0 + r;
            float4 vb = make_float4(0.f, 0.f, 0.f, 0.f);
            if (gn < N)
                vb = *reinterpret_cast<const float4*>(
                    W + (size_t)gn * K + (k0 + lk));
            Bs[lk + 0][r] = vb.x; Bs[lk + 1][r] = vb.y;
            Bs[lk + 2][r] = vb.z; Bs[lk + 3][r] = vb.w;
        }
        __syncthreads();
#pragma unroll
        for (int kk = 0; kk < 16; kk++) {
            float a[8], b[8];
            *reinterpret_cast<float4*>(&a[0]) =
                *reinterpret_cast<const float4*>(&As[kk][ty * 8]);
            *reinterpret_cast<float4*>(&a[4]) =
                *reinterpret_cast<const float4*>(&As[kk][ty * 8 + 4]);
            *reinterpret_cast<float4*>(&b[0]) =
                *reinterpret_cast<const float4*>(&Bs[kk][tx * 8]);
            *reinterpret_cast<float4*>(&b[4]) =
                *reinterpret_cast<const float4*>(&Bs[kk][tx * 8 + 4]);
#pragma unroll
            for (int i = 0; i < 8; i++)
#pragma unroll
                for (int j = 0; j < 8; j++)
                    acc[i][j] = fmaf(a[i], b[j], acc[i][j]);
        }
        __syncthreads();
    }

    // LIF epilogue: mem += impulse; spike = mem >= 1; mem reset; sum += spike
#pragma unroll
    for (int i = 0; i < 8; i++) {
        int r = row0 + ty * 8 + i;
#pragma unroll
        for (int j = 0; j < 8; j++) {
            int c = col0 + tx * 8 + j;
            if (c < N) {
                size_t idx = (size_t)r * N + c;
                float m = mem[idx] + acc[i][j];
                bool s = (m >= 1.0f);
                mem[idx] = s ? 0.0f : m;
                if (s) spksum[idx] += 1.0f;
            }
        }
    }
}

// Layer 3: one warp per batch row, W3 (10 x 1200) cached in SMEM.
__global__ __launch_bounds__(256) void layer3_kernel(
    const float* __restrict__ A /* g_sum2 */, const float* __restrict__ W3,
    float* __restrict__ out, int last)
{
    __shared__ float W3s[DOUT * HID];
    for (int i = threadIdx.x; i < DOUT * HID; i += blockDim.x)
        W3s[i] = W3[i];
    __syncthreads();

    int warp = (blockIdx.x * blockDim.x + threadIdx.x) >> 5;
    int lane = threadIdx.x & 31;
    if (warp >= BATCH) return;

    const float* a = A + (size_t)warp * HID;
    float acc[DOUT];
#pragma unroll
    for (int n = 0; n < DOUT; n++) acc[n] = 0.f;

    for (int k = lane; k < HID; k += 32) {
        float av = a[k];
#pragma unroll
        for (int n = 0; n < DOUT; n++)
            acc[n] = fmaf(av, W3s[n * HID + k], acc[n]);
    }
#pragma unroll
    for (int n = 0; n < DOUT; n++) {
#pragma unroll
        for (int off = 16; off; off >>= 1)
            acc[n] += __shfl_xor_sync(0xffffffffu, acc[n], off);
    }
    if (lane < DOUT) {
        size_t idx = (size_t)warp * DOUT + lane;
        float m = g_mem3[idx] + acc[lane];
        bool s = (m >= 1.0f);
        g_mem3[idx] = s ? 0.0f : m;
        float s3 = g_sum3[idx] + (s ? 1.0f : 0.0f);
        g_sum3[idx] = s3;
        if (last) out[idx] = s3 / 35.0f;   // match reference: exact fp32 divide
    }
}

// ---------------- host ----------------
extern "C" void kernel_launch(void* const* d_in, const int* in_sizes, int n_in,
                              void* d_out, int out_size)
{
    const float* x  = (const float*)d_in[0];
    const float* W1 = (const float*)d_in[1];
    const float* W2 = (const float*)d_in[2];
    const float* W3 = (const float*)d_in[3];
    float* out = (float*)d_out;

    float *spk, *mem1, *sum1, *mem2, *sum2;
    cudaGetSymbolAddress((void**)&spk,  g_spk);
    cudaGetSymbolAddress((void**)&mem1, g_mem1);
    cudaGetSymbolAddress((void**)&sum1, g_sum1);
    cudaGetSymbolAddress((void**)&mem2, g_mem2);
    cudaGetSymbolAddress((void**)&sum2, g_sum2);

    zero_state_kernel<<<512, 256>>>();

    const dim3 gemm_grid((HID + 127) / 128, BATCH / 128);  // (10, 64)
    const int spike_blocks = (BATCH * DIN + 255) / 256;

    for (int t = 0; t < TSTEPS; t++) {
        // kt = fold_in(key(42), t) = threefry2x32((0,42), (0,t))
        uint32_t kt0, kt1;
        threefry2x32(0u, 42u, 0u, (uint32_t)t, kt0, kt1);

        spike_gen_kernel<<<spike_blocks, 256>>>(x, kt0, kt1);
        gemm_lif_kernel<<<gemm_grid, 256>>>(spk,  W1, mem1, sum1, HID, DIN);
        gemm_lif_kernel<<<gemm_grid, 256>>>(sum1, W2, mem2, sum2, HID, HID);
        layer3_kernel<<<BATCH / 8, 256>>>(sum2, W3, out, (t == TSTEPS - 1) ? 1 : 0);
    }
}

// round 9
// speedup vs baseline: 1.0575x; 1.0575x over previous
#include <cuda_runtime.h>
#include <cstdint>
#include <cstddef>

#define BATCH  8192
#define DIN    784
#define HID    1200
#define DOUT   10
#define TSTEPS 35

// ---------------- device state (no allocs allowed) ----------------
__device__ float g_spk [(size_t)BATCH * DIN];
__device__ float g_mem1[(size_t)BATCH * HID];
__device__ float g_sum1[(size_t)BATCH * HID];
__device__ float g_mem2[(size_t)BATCH * HID];
__device__ float g_sum2[(size_t)BATCH * HID];
__device__ float g_mem3[(size_t)BATCH * DOUT];
__device__ float g_sum3[(size_t)BATCH * DOUT];

// ---------------- packed f32x2 helpers ----------------
__device__ __forceinline__ void fma2(unsigned long long& acc,
                                     unsigned long long a2, unsigned long long b2) {
    asm("fma.rn.f32x2 %0, %1, %2, %0;" : "+l"(acc) : "l"(a2), "l"(b2));
}
__device__ __forceinline__ unsigned long long bcast2(float v) {
    unsigned long long r;
    asm("mov.b64 %0, {%1, %1};" : "=l"(r) : "r"(__float_as_uint(v)));
    return r;
}

// ---------------- Threefry-2x32 (exact JAX semantics) ----------------
__host__ __device__ __forceinline__ uint32_t rotl32(uint32_t v, int r) {
#ifdef __CUDA_ARCH__
    return __funnelshift_l(v, v, r);
#else
    return (v << r) | (v >> (32 - r));
#endif
}

__host__ __device__ __forceinline__ void threefry2x32(
    uint32_t k0, uint32_t k1, uint32_t x0, uint32_t x1,
    uint32_t& o0, uint32_t& o1)
{
    uint32_t ks2 = k0 ^ k1 ^ 0x1BD11BDAu;
    x0 += k0; x1 += k1;
#define TF_R(r) { x0 += x1; x1 = rotl32(x1, (r)); x1 ^= x0; }
    TF_R(13) TF_R(15) TF_R(26) TF_R(6)
    x0 += k1;  x1 += ks2 + 1u;
    TF_R(17) TF_R(29) TF_R(16) TF_R(24)
    x0 += ks2; x1 += k0 + 2u;
    TF_R(13) TF_R(15) TF_R(26) TF_R(6)
    x0 += k0;  x1 += k1 + 3u;
    TF_R(17) TF_R(29) TF_R(16) TF_R(24)
    x0 += k1;  x1 += ks2 + 4u;
    TF_R(13) TF_R(15) TF_R(26) TF_R(6)
    x0 += ks2; x1 += k0 + 5u;
#undef TF_R
    o0 = x0; o1 = x1;
}

// ---------------- kernels ----------------
__global__ void zero_state_kernel() {
    size_t i = (size_t)blockIdx.x * blockDim.x + threadIdx.x;
    size_t stride = (size_t)gridDim.x * blockDim.x;
    size_t total = (size_t)BATCH * HID;
    for (size_t p = i; p < total; p += stride) {
        g_mem1[p] = 0.f; g_sum1[p] = 0.f;
        g_mem2[p] = 0.f; g_sum2[p] = 0.f;
    }
    if (i < (size_t)BATCH * DOUT) { g_mem3[i] = 0.f; g_sum3[i] = 0.f; }
}

// JAX threefry_partitionable bits: counter (0, i); bits = out0 ^ out1
__global__ void spike_gen_kernel(const float* __restrict__ x, uint32_t kt0, uint32_t kt1) {
    int i = blockIdx.x * blockDim.x + threadIdx.x;
    if (i >= BATCH * DIN) return;
    uint32_t y0, y1;
    threefry2x32(kt0, kt1, 0u, (uint32_t)i, y0, y1);
    uint32_t bits = y0 ^ y1;
    uint32_t fb = (bits >> 9) | 0x3f800000u;
    float u = __uint_as_float(fb) - 1.0f;
    g_spk[i] = (u * 5.0f <= x[i]) ? 1.0f : 0.0f;
}

// Fused C = A(8192 x K) @ W(N x K)^T ; then LIF update on (mem, spksum).
// Tiles 128x128x16, 256 threads, 8x8 per thread.
// Inner product uses packed fma.rn.f32x2: two independent output columns per
// instruction; each element's k-ascending RN-FMA chain is bit-identical to the
// scalar version (and to the R3 passing kernel).
__global__ __launch_bounds__(256, 1) void gemm_lif_kernel(
    const float* __restrict__ A, const float* __restrict__ W,
    float* __restrict__ mem, float* __restrict__ spksum,
    int N, int K)
{
    __shared__ float As[16][132];
    __shared__ float Bs[16][132];

    const int tid  = threadIdx.x;
    const int row0 = blockIdx.y * 128;
    const int col0 = blockIdx.x * 128;
    const int lr = tid >> 2;          // 0..63
    const int lk = (tid & 3) << 2;    // 0,4,8,12
    const int ty = tid >> 4;          // 0..15
    const int tx = tid & 15;          // 0..15

    unsigned long long acc2[8][4];
#pragma unroll
    for (int i = 0; i < 8; i++)
#pragma unroll
        for (int j = 0; j < 4; j++) acc2[i][j] = 0ull;

    for (int k0 = 0; k0 < K; k0 += 16) {
#pragma unroll
        for (int h = 0; h < 2; h++) {
            int r = lr + (h << 6);
            float4 va = *reinterpret_cast<const float4*>(
                A + (size_t)(row0 + r) * K + (k0 + lk));
            As[lk + 0][r] = va.x; As[lk + 1][r] = va.y;
            As[lk + 2][r] = va.z; As[lk + 3][r] = va.w;
            int gn = col0 + r;
            float4 vb = make_float4(0.f, 0.f, 0.f, 0.f);
            if (gn < N)
                vb = *reinterpret_cast<const float4*>(
                    W + (size_t)gn * K + (k0 + lk));
            Bs[lk + 0][r] = vb.x; Bs[lk + 1][r] = vb.y;
            Bs[lk + 2][r] = vb.z; Bs[lk + 3][r] = vb.w;
        }
        __syncthreads();
#pragma unroll
        for (int kk = 0; kk < 16; kk++) {
            float a[8];
            *reinterpret_cast<float4*>(&a[0]) =
                *reinterpret_cast<const float4*>(&As[kk][ty * 8]);
            *reinterpret_cast<float4*>(&a[4]) =
                *reinterpret_cast<const float4*>(&As[kk][ty * 8 + 4]);
            // B pairs: adjacent columns are adjacent in smem -> free packing
            ulonglong2 b01 = *reinterpret_cast<const ulonglong2*>(&Bs[kk][tx * 8]);
            ulonglong2 b23 = *reinterpret_cast<const ulonglong2*>(&Bs[kk][tx * 8 + 4]);
#pragma unroll
            for (int i = 0; i < 8; i++) {
                unsigned long long a2 = bcast2(a[i]);
                fma2(acc2[i][0], a2, b01.x);
                fma2(acc2[i][1], a2, b01.y);
                fma2(acc2[i][2], a2, b23.x);
                fma2(acc2[i][3], a2, b23.y);
            }
        }
        __syncthreads();
    }

    // LIF epilogue: mem += impulse; spike = mem >= 1; reset; sum += spike
#pragma unroll
    for (int i = 0; i < 8; i++) {
        int r = row0 + ty * 8 + i;
#pragma unroll
        for (int j = 0; j < 8; j++) {
            int c = col0 + tx * 8 + j;
            if (c < N) {
                unsigned long long p = acc2[i][j >> 1];
                float av = (j & 1) ? __uint_as_float((uint32_t)(p >> 32))
                                   : __uint_as_float((uint32_t)p);
                size_t idx = (size_t)r * N + c;
                float m = mem[idx] + av;
                bool s = (m >= 1.0f);
                mem[idx] = s ? 0.0f : m;
                if (s) spksum[idx] += 1.0f;
            }
        }
    }
}

// Layer 3: one warp per batch row, W3 (10 x 1200) cached in SMEM.
__global__ __launch_bounds__(256) void layer3_kernel(
    const float* __restrict__ A /* g_sum2 */, const float* __restrict__ W3,
    float* __restrict__ out, int last)
{
    __shared__ float W3s[DOUT * HID];
    for (int i = threadIdx.x; i < DOUT * HID; i += blockDim.x)
        W3s[i] = W3[i];
    __syncthreads();

    int warp = (blockIdx.x * blockDim.x + threadIdx.x) >> 5;
    int lane = threadIdx.x & 31;
    if (warp >= BATCH) return;

    const float* a = A + (size_t)warp * HID;
    float acc[DOUT];
#pragma unroll
    for (int n = 0; n < DOUT; n++) acc[n] = 0.f;

    for (int k = lane; k < HID; k += 32) {
        float av = a[k];
#pragma unroll
        for (int n = 0; n < DOUT; n++)
            acc[n] = fmaf(av, W3s[n * HID + k], acc[n]);
    }
#pragma unroll
    for (int n = 0; n < DOUT; n++) {
#pragma unroll
        for (int off = 16; off; off >>= 1)
            acc[n] += __shfl_xor_sync(0xffffffffu, acc[n], off);
    }
    if (lane < DOUT) {
        size_t idx = (size_t)warp * DOUT + lane;
        float m = g_mem3[idx] + acc[lane];
        bool s = (m >= 1.0f);
        g_mem3[idx] = s ? 0.0f : m;
        float s3 = g_sum3[idx] + (s ? 1.0f : 0.0f);
        g_sum3[idx] = s3;
        if (last) out[idx] = s3 / 35.0f;   // match reference: exact fp32 divide
    }
}

// ---------------- host ----------------
extern "C" void kernel_launch(void* const* d_in, const int* in_sizes, int n_in,
                              void* d_out, int out_size)
{
    const float* x  = (const float*)d_in[0];
    const float* W1 = (const float*)d_in[1];
    const float* W2 = (const float*)d_in[2];
    const float* W3 = (const float*)d_in[3];
    float* out = (float*)d_out;

    float *spk, *mem1, *sum1, *mem2, *sum2;
    cudaGetSymbolAddress((void**)&spk,  g_spk);
    cudaGetSymbolAddress((void**)&mem1, g_mem1);
    cudaGetSymbolAddress((void**)&sum1, g_sum1);
    cudaGetSymbolAddress((void**)&mem2, g_mem2);
    cudaGetSymbolAddress((void**)&sum2, g_sum2);

    zero_state_kernel<<<512, 256>>>();

    const dim3 gemm_grid((HID + 127) / 128, BATCH / 128);  // (10, 64)
    const int spike_blocks = (BATCH * DIN + 255) / 256;

    for (int t = 0; t < TSTEPS; t++) {
        // kt = fold_in(key(42), t) = threefry2x32((0,42), (0,t))
        uint32_t kt0, kt1;
        threefry2x32(0u, 42u, 0u, (uint32_t)t, kt0, kt1);

        spike_gen_kernel<<<spike_blocks, 256>>>(x, kt0, kt1);
        gemm_lif_kernel<<<gemm_grid, 256>>>(spk,  W1, mem1, sum1, HID, DIN);
        gemm_lif_kernel<<<gemm_grid, 256>>>(sum1, W2, mem2, sum2, HID, HID);
        layer3_kernel<<<BATCH / 8, 256>>>(sum2, W3, out, (t == TSTEPS - 1) ? 1 : 0);
    }
}

// round 10
// speedup vs baseline: 1.2680x; 1.1991x over previous
#include <cuda_runtime.h>
#include <cstdint>
#include <cstddef>

#define BATCH  8192
#define DIN    784
#define HID    1200
#define DOUT   10
#define TSTEPS 35

// ---------------- device state (no allocs allowed) ----------------
__device__ float g_mem1[(size_t)BATCH * HID];
__device__ float g_sum1[(size_t)BATCH * HID];
__device__ float g_mem2[(size_t)BATCH * HID];
__device__ float g_sum2[(size_t)BATCH * HID];
__device__ float g_mem3[(size_t)BATCH * DOUT];
__device__ float g_sum3[(size_t)BATCH * DOUT];
__device__ float g_W1T[(size_t)DIN * HID];            // W1 transposed: [k][n]
__device__ uint16_t g_idx[(size_t)BATCH * DIN];       // per-row ascending spike indices
__device__ int g_cnt[BATCH];

// ---------------- packed f32x2 helpers ----------------
__device__ __forceinline__ void fma2(unsigned long long& acc,
                                     unsigned long long a2, unsigned long long b2) {
    asm("fma.rn.f32x2 %0, %1, %2, %0;" : "+l"(acc) : "l"(a2), "l"(b2));
}
__device__ __forceinline__ unsigned long long bcast2(float v) {
    unsigned long long r;
    asm("mov.b64 %0, {%1, %1};" : "=l"(r) : "r"(__float_as_uint(v)));
    return r;
}
__device__ __forceinline__ float lo32(unsigned long long p) {
    return __uint_as_float((uint32_t)p);
}
__device__ __forceinline__ float hi32(unsigned long long p) {
    return __uint_as_float((uint32_t)(p >> 32));
}

// ---------------- Threefry-2x32 (exact JAX semantics) ----------------
__host__ __device__ __forceinline__ uint32_t rotl32(uint32_t v, int r) {
#ifdef __CUDA_ARCH__
    return __funnelshift_l(v, v, r);
#else
    return (v << r) | (v >> (32 - r));
#endif
}

__host__ __device__ __forceinline__ void threefry2x32(
    uint32_t k0, uint32_t k1, uint32_t x0, uint32_t x1,
    uint32_t& o0, uint32_t& o1)
{
    uint32_t ks2 = k0 ^ k1 ^ 0x1BD11BDAu;
    x0 += k0; x1 += k1;
#define TF_R(r) { x0 += x1; x1 = rotl32(x1, (r)); x1 ^= x0; }
    TF_R(13) TF_R(15) TF_R(26) TF_R(6)
    x0 += k1;  x1 += ks2 + 1u;
    TF_R(17) TF_R(29) TF_R(16) TF_R(24)
    x0 += ks2; x1 += k0 + 2u;
    TF_R(13) TF_R(15) TF_R(26) TF_R(6)
    x0 += k0;  x1 += k1 + 3u;
    TF_R(17) TF_R(29) TF_R(16) TF_R(24)
    x0 += k1;  x1 += ks2 + 4u;
    TF_R(13) TF_R(15) TF_R(26) TF_R(6)
    x0 += ks2; x1 += k0 + 5u;
#undef TF_R
    o0 = x0; o1 = x1;
}

// ---------------- kernels ----------------
__global__ void zero_state_kernel() {
    size_t i = (size_t)blockIdx.x * blockDim.x + threadIdx.x;
    size_t stride = (size_t)gridDim.x * blockDim.x;
    size_t total = (size_t)BATCH * HID;
    for (size_t p = i; p < total; p += stride) {
        g_mem1[p] = 0.f; g_sum1[p] = 0.f;
        g_mem2[p] = 0.f; g_sum2[p] = 0.f;
    }
    if (i < (size_t)BATCH * DOUT) { g_mem3[i] = 0.f; g_sum3[i] = 0.f; }
}

// W1[n][k] (HID x DIN) -> W1T[k][n]; runs once per launch
__global__ void transpose_w1_kernel(const float* __restrict__ W1) {
    int idx = blockIdx.x * blockDim.x + threadIdx.x;
    if (idx >= DIN * HID) return;
    int k = idx / HID, n = idx - k * HID;
    g_W1T[idx] = W1[(size_t)n * DIN + k];
}

// Spike gen + per-row compaction (ascending k). One warp per batch row.
// JAX threefry_partitionable bits: counter (0, i); bits = out0 ^ out1
__global__ __launch_bounds__(256) void spike_compact_kernel(
    const float* __restrict__ x, uint32_t kt0, uint32_t kt1)
{
    int warp = (blockIdx.x * blockDim.x + threadIdx.x) >> 5;
    int lane = threadIdx.x & 31;
    if (warp >= BATCH) return;
    const float* xr = x + (size_t)warp * DIN;
    uint16_t* outp = g_idx + (size_t)warp * DIN;
    int cnt = 0;
    for (int base = 0; base < DIN; base += 32) {
        int k = base + lane;
        bool p = false;
        if (k < DIN) {
            uint32_t i = (uint32_t)(warp * DIN + k);
            uint32_t y0, y1;
            threefry2x32(kt0, kt1, 0u, i, y0, y1);
            uint32_t bits = y0 ^ y1;
            uint32_t fb = (bits >> 9) | 0x3f800000u;
            float u = __uint_as_float(fb) - 1.0f;
            p = (u * 5.0f <= xr[k]);
        }
        unsigned mask = __ballot_sync(0xffffffffu, p);
        if (p) outp[cnt + __popc(mask & ((1u << lane) - 1))] = (uint16_t)k;
        cnt += __popc(mask);
    }
    if (lane == 0) g_cnt[warp] = cnt;
}

// Layer 1 sparse: C[r,n] = sum over active k (ascending) of W1T[k,n].
// Bit-identical to the dense ascending-k FMA chain (fma(0,w,acc)==acc,
// fma(1,w,acc)==RN(w+acc)). 2 threads per row, 16 cols per row.
#define NC1       16
#define L1_STRIDE 20   // floats per k-row in smem (80B; k*20%32 spreads banks)
__global__ __launch_bounds__(256, 1) void layer1_sparse_kernel(
    float* __restrict__ mem, float* __restrict__ spksum)
{
    extern __shared__ float sW[];   // DIN * L1_STRIDE floats
    const int tid = threadIdx.x;
    const int c0 = blockIdx.y * NC1;

    // stage W1T[:, c0:c0+16]
    for (int idx = tid; idx < DIN * 4; idx += 256) {
        int k = idx >> 2, q = idx & 3;
        float4 v = *reinterpret_cast<const float4*>(
            &g_W1T[(size_t)k * HID + c0 + q * 4]);
        *reinterpret_cast<float4*>(&sW[k * L1_STRIDE + q * 4]) = v;
    }
    __syncthreads();

    const int row  = blockIdx.x * 128 + (tid >> 1);
    const int half = tid & 1;            // cols half*8 .. half*8+7
    const int n = g_cnt[row];
    const uint16_t* il = g_idx + (size_t)row * DIN;
    const unsigned long long ones = 0x3f8000003f800000ull;

    unsigned long long acc[4] = {0ull, 0ull, 0ull, 0ull};
    for (int i = 0; i < n; i++) {
        int k = il[i];
        const float* wp = &sW[k * L1_STRIDE + half * 8];
        ulonglong2 w0 = *reinterpret_cast<const ulonglong2*>(wp);
        ulonglong2 w1 = *reinterpret_cast<const ulonglong2*>(wp + 4);
        fma2(acc[0], w0.x, ones);
        fma2(acc[1], w0.y, ones);
        fma2(acc[2], w1.x, ones);
        fma2(acc[3], w1.y, ones);
    }

    // LIF epilogue on 8 cols
    size_t base = (size_t)row * HID + c0 + half * 8;
#pragma unroll
    for (int q = 0; q < 2; q++) {
        float av[4] = { lo32(acc[2 * q]), hi32(acc[2 * q]),
                        lo32(acc[2 * q + 1]), hi32(acc[2 * q + 1]) };
        float4 m = *reinterpret_cast<float4*>(mem + base + q * 4);
        float4 sv = *reinterpret_cast<float4*>(spksum + base + q * 4);
        float* mp = &m.x; float* sp = &sv.x;
#pragma unroll
        for (int e = 0; e < 4; e++) {
            float v = mp[e] + av[e];
            bool s = (v >= 1.0f);
            mp[e] = s ? 0.0f : v;
            if (s) sp[e] += 1.0f;
        }
        *reinterpret_cast<float4*>(mem + base + q * 4) = m;
        *reinterpret_cast<float4*>(spksum + base + q * 4) = sv;
    }
}

// Dense fused C = A(8192 x K) @ W(N x K)^T ; then LIF update.
// Tiles 128x128x16, 256 threads, 8x8 per thread; packed f32x2 FMAs.
// Per-thread cols remapped to {tx*4..+3} u {64+tx*4..+3} so the two B
// LDS.128 are contiguous per octet -> bank-conflict-free. Per-element
// FMA chains unchanged -> bit-exact.
__global__ __launch_bounds__(256, 1) void gemm_lif_kernel(
    const float* __restrict__ A, const float* __restrict__ W,
    float* __restrict__ mem, float* __restrict__ spksum,
    int N, int K)
{
    __shared__ float As[16][132];
    __shared__ float Bs[16][132];

    const int tid  = threadIdx.x;
    const int row0 = blockIdx.y * 128;
    const int col0 = blockIdx.x * 128;
    const int lr = tid >> 2;          // 0..63
    const int lk = (tid & 3) << 2;    // 0,4,8,12
    const int ty = tid >> 4;          // 0..15
    const int tx = tid & 15;          // 0..15

    unsigned long long acc2[8][4];
#pragma unroll
    for (int i = 0; i < 8; i++)
#pragma unroll
        for (int j = 0; j < 4; j++) acc2[i][j] = 0ull;

    for (int k0 = 0; k0 < K; k0 += 16) {
#pragma unroll
        for (int h = 0; h < 2; h++) {
            int r = lr + (h << 6);
            float4 va = *reinterpret_cast<const float4*>(
                A + (size_t)(row0 + r) * K + (k0 + lk));
            As[lk + 0][r] = va.x; As[lk + 1][r] = va.y;
            As[lk + 2][r] = va.z; As[lk + 3][r] = va.w;
            int gn = col0 + r;
            float4 vb = make_float4(0.f, 0.f, 0.f, 0.f);
            if (gn < N)
                vb = *reinterpret_cast<const float4*>(
                    W + (size_t)gn * K + (k0 + lk));
            Bs[lk + 0][r] = vb.x; Bs[lk + 1][r] = vb.y;
            Bs[lk + 2][r] = vb.z; Bs[lk + 3][r] = vb.w;
        }
        __syncthreads();
#pragma unroll
        for (int kk = 0; kk < 16; kk++) {
            float a[8];
            *reinterpret_cast<float4*>(&a[0]) =
                *reinterpret_cast<const float4*>(&As[kk][ty * 8]);
            *reinterpret_cast<float4*>(&a[4]) =
                *reinterpret_cast<const float4*>(&As[kk][ty * 8 + 4]);
            // conflict-free: octet covers 128 contiguous bytes
            ulonglong2 b01 = *reinterpret_cast<const ulonglong2*>(&Bs[kk][tx * 4]);
            ulonglong2 b23 = *reinterpret_cast<const ulonglong2*>(&Bs[kk][64 + tx * 4]);
#pragma unroll
            for (int i = 0; i < 8; i++) {
                unsigned long long a2 = bcast2(a[i]);
                fma2(acc2[i][0], a2, b01.x);
                fma2(acc2[i][1], a2, b01.y);
                fma2(acc2[i][2], a2, b23.x);
                fma2(acc2[i][3], a2, b23.y);
            }
        }
        __syncthreads();
    }

    // LIF epilogue: mem += impulse; spike = mem >= 1; reset; sum += spike
#pragma unroll
    for (int i = 0; i < 8; i++) {
        int r = row0 + ty * 8 + i;
#pragma unroll
        for (int hb = 0; hb < 2; hb++) {
            int cbase = col0 + hb * 64 + tx * 4;
            if (cbase < N) {
                float av[4] = { lo32(acc2[i][2 * hb]),     hi32(acc2[i][2 * hb]),
                                lo32(acc2[i][2 * hb + 1]), hi32(acc2[i][2 * hb + 1]) };
                size_t idx = (size_t)r * N + cbase;
                float4 m = *reinterpret_cast<float4*>(mem + idx);
                float4 sv = *reinterpret_cast<float4*>(spksum + idx);
                float* mp = &m.x; float* sp = &sv.x;
#pragma unroll
                for (int e = 0; e < 4; e++) {
                    float v = mp[e] + av[e];
                    bool s = (v >= 1.0f);
                    mp[e] = s ? 0.0f : v;
                    if (s) sp[e] += 1.0f;
                }
                *reinterpret_cast<float4*>(mem + idx) = m;
                *reinterpret_cast<float4*>(spksum + idx) = sv;
            }
        }
    }
}

// Layer 3: one warp per batch row, W3 (10 x 1200) cached in SMEM.
__global__ __launch_bounds__(256) void layer3_kernel(
    const float* __restrict__ A /* g_sum2 */, const float* __restrict__ W3,
    float* __restrict__ out, int last)
{
    __shared__ float W3s[DOUT * HID];
    for (int i = threadIdx.x; i < DOUT * HID; i += blockDim.x)
        W3s[i] = W3[i];
    __syncthreads();

    int warp = (blockIdx.x * blockDim.x + threadIdx.x) >> 5;
    int lane = threadIdx.x & 31;
    if (warp >= BATCH) return;

    const float* a = A + (size_t)warp * HID;
    float acc[DOUT];
#pragma unroll
    for (int n = 0; n < DOUT; n++) acc[n] = 0.f;

    for (int k = lane; k < HID; k += 32) {
        float av = a[k];
#pragma unroll
        for (int n = 0; n < DOUT; n++)
            acc[n] = fmaf(av, W3s[n * HID + k], acc[n]);
    }
#pragma unroll
    for (int n = 0; n < DOUT; n++) {
#pragma unroll
        for (int off = 16; off; off >>= 1)
            acc[n] += __shfl_xor_sync(0xffffffffu, acc[n], off);
    }
    if (lane < DOUT) {
        size_t idx = (size_t)warp * DOUT + lane;
        float m = g_mem3[idx] + acc[lane];
        bool s = (m >= 1.0f);
        g_mem3[idx] = s ? 0.0f : m;
        float s3 = g_sum3[idx] + (s ? 1.0f : 0.0f);
        g_sum3[idx] = s3;
        if (last) out[idx] = s3 / 35.0f;   // match reference: exact fp32 divide
    }
}

// ---------------- host ----------------
extern "C" void kernel_launch(void* const* d_in, const int* in_sizes, int n_in,
                              void* d_out, int out_size)
{
    const float* x  = (const float*)d_in[0];
    const float* W1 = (const float*)d_in[1];
    const float* W2 = (const float*)d_in[2];
    const float* W3 = (const float*)d_in[3];
    float* out = (float*)d_out;

    float *mem1, *sum1, *mem2, *sum2;
    cudaGetSymbolAddress((void**)&mem1, g_mem1);
    cudaGetSymbolAddress((void**)&sum1, g_sum1);
    cudaGetSymbolAddress((void**)&mem2, g_mem2);
    cudaGetSymbolAddress((void**)&sum2, g_sum2);

    const int l1_smem = DIN * L1_STRIDE * sizeof(float);   // 62720 B
    cudaFuncSetAttribute(layer1_sparse_kernel,
                         cudaFuncAttributeMaxDynamicSharedMemorySize, l1_smem);

    zero_state_kernel<<<512, 256>>>();
    transpose_w1_kernel<<<(DIN * HID + 255) / 256, 256>>>(W1);

    const dim3 l1_grid(BATCH / 128, HID / NC1);            // (64, 75)
    const dim3 gemm_grid((HID + 127) / 128, BATCH / 128);  // (10, 64)

    for (int t = 0; t < TSTEPS; t++) {
        // kt = fold_in(key(42), t) = threefry2x32((0,42), (0,t))
        uint32_t kt0, kt1;
        threefry2x32(0u, 42u, 0u, (uint32_t)t, kt0, kt1);

        spike_compact_kernel<<<BATCH / 8, 256>>>(x, kt0, kt1);
        layer1_sparse_kernel<<<l1_grid, 256, l1_smem>>>(mem1, sum1);
        gemm_lif_kernel<<<gemm_grid, 256>>>(sum1, W2, mem2, sum2, HID, HID);
        layer3_kernel<<<BATCH / 8, 256>>>(sum2, W3, out, (t == TSTEPS - 1) ? 1 : 0);
    }
}

// round 11
// speedup vs baseline: 1.3491x; 1.0640x over previous
#include <cuda_runtime.h>
#include <cstdint>
#include <cstddef>

#define BATCH  8192
#define DIN    784
#define HID    1200
#define DOUT   10
#define TSTEPS 35

// ---------------- device state (no allocs allowed) ----------------
__device__ float g_mem1[(size_t)BATCH * HID];
__device__ float g_sum1[(size_t)BATCH * HID];
__device__ float g_mem2[(size_t)BATCH * HID];
__device__ float g_sum2[(size_t)BATCH * HID];
__device__ float g_mem3[(size_t)BATCH * DOUT];
__device__ float g_sum3[(size_t)BATCH * DOUT];
__device__ float g_W1T[(size_t)DIN * HID];            // W1 transposed: [k][n]
__device__ uint16_t g_idx[(size_t)BATCH * DIN];       // per-row ascending spike indices
__device__ int g_cnt[BATCH];

// ---------------- packed f32x2 helpers ----------------
__device__ __forceinline__ void fma2(unsigned long long& acc,
                                     unsigned long long a2, unsigned long long b2) {
    asm("fma.rn.f32x2 %0, %1, %2, %0;" : "+l"(acc) : "l"(a2), "l"(b2));
}
__device__ __forceinline__ unsigned long long bcast2(float v) {
    unsigned long long r;
    asm("mov.b64 %0, {%1, %1};" : "=l"(r) : "r"(__float_as_uint(v)));
    return r;
}
__device__ __forceinline__ float lo32(unsigned long long p) {
    return __uint_as_float((uint32_t)p);
}
__device__ __forceinline__ float hi32(unsigned long long p) {
    return __uint_as_float((uint32_t)(p >> 32));
}

// ---------------- Threefry-2x32 (exact JAX semantics) ----------------
__host__ __device__ __forceinline__ uint32_t rotl32(uint32_t v, int r) {
#ifdef __CUDA_ARCH__
    return __funnelshift_l(v, v, r);
#else
    return (v << r) | (v >> (32 - r));
#endif
}

__host__ __device__ __forceinline__ void threefry2x32(
    uint32_t k0, uint32_t k1, uint32_t x0, uint32_t x1,
    uint32_t& o0, uint32_t& o1)
{
    uint32_t ks2 = k0 ^ k1 ^ 0x1BD11BDAu;
    x0 += k0; x1 += k1;
#define TF_R(r) { x0 += x1; x1 = rotl32(x1, (r)); x1 ^= x0; }
    TF_R(13) TF_R(15) TF_R(26) TF_R(6)
    x0 += k1;  x1 += ks2 + 1u;
    TF_R(17) TF_R(29) TF_R(16) TF_R(24)
    x0 += ks2; x1 += k0 + 2u;
    TF_R(13) TF_R(15) TF_R(26) TF_R(6)
    x0 += k0;  x1 += k1 + 3u;
    TF_R(17) TF_R(29) TF_R(16) TF_R(24)
    x0 += k1;  x1 += ks2 + 4u;
    TF_R(13) TF_R(15) TF_R(26) TF_R(6)
    x0 += ks2; x1 += k0 + 5u;
#undef TF_R
    o0 = x0; o1 = x1;
}

// ---------------- kernels ----------------
__global__ void zero_state_kernel() {
    size_t i = (size_t)blockIdx.x * blockDim.x + threadIdx.x;
    size_t stride = (size_t)gridDim.x * blockDim.x;
    size_t total = (size_t)BATCH * HID;
    for (size_t p = i; p < total; p += stride) {
        g_mem1[p] = 0.f; g_sum1[p] = 0.f;
        g_mem2[p] = 0.f; g_sum2[p] = 0.f;
    }
    if (i < (size_t)BATCH * DOUT) { g_mem3[i] = 0.f; g_sum3[i] = 0.f; }
}

// W1[n][k] (HID x DIN) -> W1T[k][n]; runs once per launch
__global__ void transpose_w1_kernel(const float* __restrict__ W1) {
    int idx = blockIdx.x * blockDim.x + threadIdx.x;
    if (idx >= DIN * HID) return;
    int k = idx / HID, n = idx - k * HID;
    g_W1T[idx] = W1[(size_t)n * DIN + k];
}

// Spike gen + per-row compaction (ascending k). One warp per batch row.
// JAX threefry_partitionable bits: counter (0, i); bits = out0 ^ out1
__global__ __launch_bounds__(256) void spike_compact_kernel(
    const float* __restrict__ x, uint32_t kt0, uint32_t kt1)
{
    int warp = (blockIdx.x * blockDim.x + threadIdx.x) >> 5;
    int lane = threadIdx.x & 31;
    if (warp >= BATCH) return;
    const float* xr = x + (size_t)warp * DIN;
    uint16_t* outp = g_idx + (size_t)warp * DIN;
    int cnt = 0;
    for (int base = 0; base < DIN; base += 32) {
        int k = base + lane;
        bool p = false;
        if (k < DIN) {
            uint32_t i = (uint32_t)(warp * DIN + k);
            uint32_t y0, y1;
            threefry2x32(kt0, kt1, 0u, i, y0, y1);
            uint32_t bits = y0 ^ y1;
            uint32_t fb = (bits >> 9) | 0x3f800000u;
            float u = __uint_as_float(fb) - 1.0f;
            p = (u * 5.0f <= xr[k]);
        }
        unsigned mask = __ballot_sync(0xffffffffu, p);
        if (p) outp[cnt + __popc(mask & ((1u << lane) - 1))] = (uint16_t)k;
        cnt += __popc(mask);
    }
    if (lane == 0) g_cnt[warp] = cnt;
}

// Layer 1 sparse: C[r,n] = sum over active k (ascending) of W1T[k,n].
// Bit-identical to the dense ascending-k FMA chain (fma(0,w,acc)==acc,
// fma(1,w,acc)==RN(w+acc)). One thread per row handles all 16 cols of the
// block's column slice; depth-1 software pipeline hides il->LDS latency.
#define NC1       16
#define L1_STRIDE 20   // floats per k-row in smem (80B; k*20%32 spreads banks)
__global__ __launch_bounds__(256, 1) void layer1_sparse_kernel(
    float* __restrict__ mem, float* __restrict__ spksum)
{
    extern __shared__ float sW[];   // DIN * L1_STRIDE floats
    const int tid = threadIdx.x;
    const int c0 = blockIdx.y * NC1;

    // stage W1T[:, c0:c0+16]
    for (int idx = tid; idx < DIN * 4; idx += 256) {
        int k = idx >> 2, q = idx & 3;
        float4 v = *reinterpret_cast<const float4*>(
            &g_W1T[(size_t)k * HID + c0 + q * 4]);
        *reinterpret_cast<float4*>(&sW[k * L1_STRIDE + q * 4]) = v;
    }
    __syncthreads();

    const int row = blockIdx.x * 256 + tid;
    const int n = g_cnt[row];
    const uint16_t* il = g_idx + (size_t)row * DIN;
    const unsigned long long ones = 0x3f8000003f800000ull;

    unsigned long long acc[8];
#pragma unroll
    for (int j = 0; j < 8; j++) acc[j] = 0ull;

    if (n > 0) {
        int k = il[0];
        const float* wp = &sW[k * L1_STRIDE];
        ulonglong2 wA0 = *reinterpret_cast<const ulonglong2*>(wp);
        ulonglong2 wA1 = *reinterpret_cast<const ulonglong2*>(wp + 4);
        ulonglong2 wA2 = *reinterpret_cast<const ulonglong2*>(wp + 8);
        ulonglong2 wA3 = *reinterpret_cast<const ulonglong2*>(wp + 12);
        for (int i = 0; i < n; i++) {
            // prefetch next spike's weights (index clamp keeps reads in-bounds)
            int inext = (i + 1 < n) ? (i + 1) : (n - 1);
            int kn = il[inext];
            const float* np = &sW[kn * L1_STRIDE];
            ulonglong2 nb0 = *reinterpret_cast<const ulonglong2*>(np);
            ulonglong2 nb1 = *reinterpret_cast<const ulonglong2*>(np + 4);
            ulonglong2 nb2 = *reinterpret_cast<const ulonglong2*>(np + 8);
            ulonglong2 nb3 = *reinterpret_cast<const ulonglong2*>(np + 12);
            // consume current (resident) weights
            fma2(acc[0], wA0.x, ones);
            fma2(acc[1], wA0.y, ones);
            fma2(acc[2], wA1.x, ones);
            fma2(acc[3], wA1.y, ones);
            fma2(acc[4], wA2.x, ones);
            fma2(acc[5], wA2.y, ones);
            fma2(acc[6], wA3.x, ones);
            fma2(acc[7], wA3.y, ones);
            wA0 = nb0; wA1 = nb1; wA2 = nb2; wA3 = nb3;
        }
    }

    // LIF epilogue on 16 cols
    size_t base = (size_t)row * HID + c0;
#pragma unroll
    for (int q = 0; q < 4; q++) {
        float av[4] = { lo32(acc[2 * q]), hi32(acc[2 * q]),
                        lo32(acc[2 * q + 1]), hi32(acc[2 * q + 1]) };
        float4 m = *reinterpret_cast<float4*>(mem + base + q * 4);
        float4 sv = *reinterpret_cast<float4*>(spksum + base + q * 4);
        float* mp = &m.x; float* sp = &sv.x;
#pragma unroll
        for (int e = 0; e < 4; e++) {
            float v = mp[e] + av[e];
            bool s = (v >= 1.0f);
            mp[e] = s ? 0.0f : v;
            if (s) sp[e] += 1.0f;
        }
        *reinterpret_cast<float4*>(mem + base + q * 4) = m;
        *reinterpret_cast<float4*>(spksum + base + q * 4) = sv;
    }
}

// Dense fused C = A(8192 x K) @ W(N x K)^T ; then LIF update.
// Tiles 128x128x16, 256 threads, 8x8 per thread; packed f32x2 FMAs.
// Per-thread cols {tx*4..+3} u {64+tx*4..+3}: conflict-free B LDS.128.
__global__ __launch_bounds__(256, 1) void gemm_lif_kernel(
    const float* __restrict__ A, const float* __restrict__ W,
    float* __restrict__ mem, float* __restrict__ spksum,
    int N, int K)
{
    __shared__ float As[16][132];
    __shared__ float Bs[16][132];

    const int tid  = threadIdx.x;
    const int row0 = blockIdx.y * 128;
    const int col0 = blockIdx.x * 128;
    const int lr = tid >> 2;          // 0..63
    const int lk = (tid & 3) << 2;    // 0,4,8,12
    const int ty = tid >> 4;          // 0..15
    const int tx = tid & 15;          // 0..15

    unsigned long long acc2[8][4];
#pragma unroll
    for (int i = 0; i < 8; i++)
#pragma unroll
        for (int j = 0; j < 4; j++) acc2[i][j] = 0ull;

    for (int k0 = 0; k0 < K; k0 += 16) {
#pragma unroll
        for (int h = 0; h < 2; h++) {
            int r = lr + (h << 6);
            float4 va = *reinterpret_cast<const float4*>(
                A + (size_t)(row0 + r) * K + (k0 + lk));
            As[lk + 0][r] = va.x; As[lk + 1][r] = va.y;
            As[lk + 2][r] = va.z; As[lk + 3][r] = va.w;
            int gn = col0 + r;
            float4 vb = make_float4(0.f, 0.f, 0.f, 0.f);
            if (gn < N)
                vb = *reinterpret_cast<const float4*>(
                    W + (size_t)gn * K + (k0 + lk));
            Bs[lk + 0][r] = vb.x; Bs[lk + 1][r] = vb.y;
            Bs[lk + 2][r] = vb.z; Bs[lk + 3][r] = vb.w;
        }
        __syncthreads();
#pragma unroll
        for (int kk = 0; kk < 16; kk++) {
            float a[8];
            *reinterpret_cast<float4*>(&a[0]) =
                *reinterpret_cast<const float4*>(&As[kk][ty * 8]);
            *reinterpret_cast<float4*>(&a[4]) =
                *reinterpret_cast<const float4*>(&As[kk][ty * 8 + 4]);
            ulonglong2 b01 = *reinterpret_cast<const ulonglong2*>(&Bs[kk][tx * 4]);
            ulonglong2 b23 = *reinterpret_cast<const ulonglong2*>(&Bs[kk][64 + tx * 4]);
#pragma unroll
            for (int i = 0; i < 8; i++) {
                unsigned long long a2 = bcast2(a[i]);
                fma2(acc2[i][0], a2, b01.x);
                fma2(acc2[i][1], a2, b01.y);
                fma2(acc2[i][2], a2, b23.x);
                fma2(acc2[i][3], a2, b23.y);
            }
        }
        __syncthreads();
    }

    // LIF epilogue: mem += impulse; spike = mem >= 1; reset; sum += spike
#pragma unroll
    for (int i = 0; i < 8; i++) {
        int r = row0 + ty * 8 + i;
#pragma unroll
        for (int hb = 0; hb < 2; hb++) {
            int cbase = col0 + hb * 64 + tx * 4;
            if (cbase < N) {
                float av[4] = { lo32(acc2[i][2 * hb]),     hi32(acc2[i][2 * hb]),
                                lo32(acc2[i][2 * hb + 1]), hi32(acc2[i][2 * hb + 1]) };
                size_t idx = (size_t)r * N + cbase;
                float4 m = *reinterpret_cast<float4*>(mem + idx);
                float4 sv = *reinterpret_cast<float4*>(spksum + idx);
                float* mp = &m.x; float* sp = &sv.x;
#pragma unroll
                for (int e = 0; e < 4; e++) {
                    float v = mp[e] + av[e];
                    bool s = (v >= 1.0f);
                    mp[e] = s ? 0.0f : v;
                    if (s) sp[e] += 1.0f;
                }
                *reinterpret_cast<float4*>(mem + idx) = m;
                *reinterpret_cast<float4*>(spksum + idx) = sv;
            }
        }
    }
}

// Layer 3: one warp per batch row, W3 (10 x 1200) cached in SMEM.
__global__ __launch_bounds__(256) void layer3_kernel(
    const float* __restrict__ A /* g_sum2 */, const float* __restrict__ W3,
    float* __restrict__ out, int last)
{
    __shared__ float W3s[DOUT * HID];
    for (int i = threadIdx.x; i < DOUT * HID; i += blockDim.x)
        W3s[i] = W3[i];
    __syncthreads();

    int warp = (blockIdx.x * blockDim.x + threadIdx.x) >> 5;
    int lane = threadIdx.x & 31;
    if (warp >= BATCH) return;

    const float* a = A + (size_t)warp * HID;
    float acc[DOUT];
#pragma unroll
    for (int n = 0; n < DOUT; n++) acc[n] = 0.f;

    for (int k = lane; k < HID; k += 32) {
        float av = a[k];
#pragma unroll
        for (int n = 0; n < DOUT; n++)
            acc[n] = fmaf(av, W3s[n * HID + k], acc[n]);
    }
#pragma unroll
    for (int n = 0; n < DOUT; n++) {
#pragma unroll
        for (int off = 16; off; off >>= 1)
            acc[n] += __shfl_xor_sync(0xffffffffu, acc[n], off);
    }
    if (lane < DOUT) {
        size_t idx = (size_t)warp * DOUT + lane;
        float m = g_mem3[idx] + acc[lane];
        bool s = (m >= 1.0f);
        g_mem3[idx] = s ? 0.0f : m;
        float s3 = g_sum3[idx] + (s ? 1.0f : 0.0f);
        g_sum3[idx] = s3;
        if (last) out[idx] = s3 / 35.0f;   // match reference: exact fp32 divide
    }
}

// ---------------- host ----------------
extern "C" void kernel_launch(void* const* d_in, const int* in_sizes, int n_in,
                              void* d_out, int out_size)
{
    const float* x  = (const float*)d_in[0];
    const float* W1 = (const float*)d_in[1];
    const float* W2 = (const float*)d_in[2];
    const float* W3 = (const float*)d_in[3];
    float* out = (float*)d_out;

    float *mem1, *sum1, *mem2, *sum2;
    cudaGetSymbolAddress((void**)&mem1, g_mem1);
    cudaGetSymbolAddress((void**)&sum1, g_sum1);
    cudaGetSymbolAddress((void**)&mem2, g_mem2);
    cudaGetSymbolAddress((void**)&sum2, g_sum2);

    const int l1_smem = DIN * L1_STRIDE * sizeof(float);   // 62720 B
    cudaFuncSetAttribute(layer1_sparse_kernel,
                         cudaFuncAttributeMaxDynamicSharedMemorySize, l1_smem);

    zero_state_kernel<<<512, 256>>>();
    transpose_w1_kernel<<<(DIN * HID + 255) / 256, 256>>>(W1);

    const dim3 l1_grid(BATCH / 256, HID / NC1);            // (32, 75)
    const dim3 gemm_grid((HID + 127) / 128, BATCH / 128);  // (10, 64)

    for (int t = 0; t < TSTEPS; t++) {
        // kt = fold_in(key(42), t) = threefry2x32((0,42), (0,t))
        uint32_t kt0, kt1;
        threefry2x32(0u, 42u, 0u, (uint32_t)t, kt0, kt1);

        spike_compact_kernel<<<BATCH / 8, 256>>>(x, kt0, kt1);
        layer1_sparse_kernel<<<l1_grid, 256, l1_smem>>>(mem1, sum1);
        gemm_lif_kernel<<<gemm_grid, 256>>>(sum1, W2, mem2, sum2, HID, HID);
        layer3_kernel<<<BATCH / 8, 256>>>(sum2, W3, out, (t == TSTEPS - 1) ? 1 : 0);
    }
}

// round 12
// speedup vs baseline: 1.4490x; 1.0740x over previous
#include <cuda_runtime.h>
#include <cstdint>
#include <cstddef>

#define BATCH  8192
#define DIN    784
#define HID    1200
#define DOUT   10
#define TSTEPS 35

// ---------------- device state (no allocs allowed) ----------------
__device__ float g_mem1[(size_t)BATCH * HID];
__device__ float g_sum1[(size_t)BATCH * HID];
__device__ float g_mem2[(size_t)BATCH * HID];
__device__ float g_sum2[(size_t)BATCH * HID];
__device__ float g_mem3[(size_t)BATCH * DOUT];
__device__ float g_sum3[(size_t)BATCH * DOUT];
__device__ float g_W1T[(size_t)DIN * HID];            // W1 transposed: [k][n]
__device__ uint16_t g_idx[(size_t)BATCH * DIN];       // per-row ascending spike indices
__device__ int g_cnt[BATCH];

// ---------------- packed f32x2 helpers ----------------
__device__ __forceinline__ void fma2(unsigned long long& acc,
                                     unsigned long long a2, unsigned long long b2) {
    asm("fma.rn.f32x2 %0, %1, %2, %0;" : "+l"(acc) : "l"(a2), "l"(b2));
}
__device__ __forceinline__ unsigned long long bcast2(float v) {
    unsigned long long r;
    asm("mov.b64 %0, {%1, %1};" : "=l"(r) : "r"(__float_as_uint(v)));
    return r;
}
__device__ __forceinline__ float lo32(unsigned long long p) {
    return __uint_as_float((uint32_t)p);
}
__device__ __forceinline__ float hi32(unsigned long long p) {
    return __uint_as_float((uint32_t)(p >> 32));
}

// ---------------- Threefry-2x32 (exact JAX semantics) ----------------
__host__ __device__ __forceinline__ uint32_t rotl32(uint32_t v, int r) {
#ifdef __CUDA_ARCH__
    return __funnelshift_l(v, v, r);
#else
    return (v << r) | (v >> (32 - r));
#endif
}

__host__ __device__ __forceinline__ void threefry2x32(
    uint32_t k0, uint32_t k1, uint32_t x0, uint32_t x1,
    uint32_t& o0, uint32_t& o1)
{
    uint32_t ks2 = k0 ^ k1 ^ 0x1BD11BDAu;
    x0 += k0; x1 += k1;
#define TF_R(r) { x0 += x1; x1 = rotl32(x1, (r)); x1 ^= x0; }
    TF_R(13) TF_R(15) TF_R(26) TF_R(6)
    x0 += k1;  x1 += ks2 + 1u;
    TF_R(17) TF_R(29) TF_R(16) TF_R(24)
    x0 += ks2; x1 += k0 + 2u;
    TF_R(13) TF_R(15) TF_R(26) TF_R(6)
    x0 += k0;  x1 += k1 + 3u;
    TF_R(17) TF_R(29) TF_R(16) TF_R(24)
    x0 += k1;  x1 += ks2 + 4u;
    TF_R(13) TF_R(15) TF_R(26) TF_R(6)
    x0 += ks2; x1 += k0 + 5u;
#undef TF_R
    o0 = x0; o1 = x1;
}

// ---------------- kernels ----------------
__global__ void zero_state_kernel() {
    size_t i = (size_t)blockIdx.x * blockDim.x + threadIdx.x;
    size_t stride = (size_t)gridDim.x * blockDim.x;
    size_t total = (size_t)BATCH * HID;
    for (size_t p = i; p < total; p += stride) {
        g_mem1[p] = 0.f; g_sum1[p] = 0.f;
        g_mem2[p] = 0.f; g_sum2[p] = 0.f;
    }
    if (i < (size_t)BATCH * DOUT) { g_mem3[i] = 0.f; g_sum3[i] = 0.f; }
}

// W1[n][k] (HID x DIN) -> W1T[k][n]; runs once per launch
__global__ void transpose_w1_kernel(const float* __restrict__ W1) {
    int idx = blockIdx.x * blockDim.x + threadIdx.x;
    if (idx >= DIN * HID) return;
    int k = idx / HID, n = idx - k * HID;
    g_W1T[idx] = W1[(size_t)n * DIN + k];
}

// Spike gen + per-row compaction (ascending k). One warp per batch row.
// JAX threefry_partitionable bits: counter (0, i); bits = out0 ^ out1
__global__ __launch_bounds__(256) void spike_compact_kernel(
    const float* __restrict__ x, uint32_t kt0, uint32_t kt1)
{
    int warp = (blockIdx.x * blockDim.x + threadIdx.x) >> 5;
    int lane = threadIdx.x & 31;
    if (warp >= BATCH) return;
    const float* xr = x + (size_t)warp * DIN;
    uint16_t* outp = g_idx + (size_t)warp * DIN;
    int cnt = 0;
    for (int base = 0; base < DIN; base += 32) {
        int k = base + lane;
        bool p = false;
        if (k < DIN) {
            uint32_t i = (uint32_t)(warp * DIN + k);
            uint32_t y0, y1;
            threefry2x32(kt0, kt1, 0u, i, y0, y1);
            uint32_t bits = y0 ^ y1;
            uint32_t fb = (bits >> 9) | 0x3f800000u;
            float u = __uint_as_float(fb) - 1.0f;
            p = (u * 5.0f <= xr[k]);
        }
        unsigned mask = __ballot_sync(0xffffffffu, p);
        if (p) outp[cnt + __popc(mask & ((1u << lane) - 1))] = (uint16_t)k;
        cnt += __popc(mask);
    }
    if (lane == 0) g_cnt[warp] = cnt;
}

// Layer 1 sparse, warp-per-row broadcast layout:
// C[r,n] = sum over active k (ascending) of W1T[k,n]. All 32 lanes of a warp
// share the SAME spike k (conflict-free broadcast LDS; consecutive 8B/lane);
// each lane owns 2 adjacent columns (one fma2). Ascending-k RN chain per
// column is unchanged -> bit-exact. Depth-2 index / depth-1 weight pipeline.
#define NC1 64
__global__ __launch_bounds__(512, 1) void layer1_sparse_kernel(
    float* __restrict__ mem, float* __restrict__ spksum)
{
    extern __shared__ float sW[];   // DIN * NC1 floats (200704 B)
    const int tid = threadIdx.x;
    const int c0 = blockIdx.y * NC1;

    // stage W1T[:, c0:c0+64] (rows of 64 consecutive floats)
    for (int idx = tid; idx < DIN * (NC1 / 4); idx += 512) {
        int k = idx / (NC1 / 4), q = idx - k * (NC1 / 4);
        int c = c0 + q * 4;
        float4 v = make_float4(0.f, 0.f, 0.f, 0.f);
        if (c + 3 < HID)
            v = *reinterpret_cast<const float4*>(&g_W1T[(size_t)k * HID + c]);
        *reinterpret_cast<float4*>(&sW[k * NC1 + q * 4]) = v;
    }
    __syncthreads();

    const int wrp  = tid >> 5;
    const int lane = tid & 31;
    const int c = c0 + lane * 2;
    const bool valid = (c < HID);
    const unsigned long long ones = 0x3f8000003f800000ull;

    for (int rl = 0; rl < 32; rl++) {
        const int row = blockIdx.x * 512 + wrp * 32 + rl;
        const int n = g_cnt[row];
        const uint16_t* il = g_idx + (size_t)row * DIN;

        unsigned long long acc = 0ull;
        if (n > 0) {
            int k1 = il[0];
            int k2 = (n > 1) ? il[1] : k1;
            unsigned long long w = *reinterpret_cast<const unsigned long long*>(
                &sW[k1 * NC1 + lane * 2]);
            for (int i = 0; i < n; i++) {
                int k3 = (i + 2 < n) ? il[i + 2] : k2;       // LDG (uniform)
                unsigned long long wn = *reinterpret_cast<const unsigned long long*>(
                    &sW[k2 * NC1 + lane * 2]);               // LDS for i+1
                fma2(acc, w, ones);
                w = wn; k2 = k3;
            }
        }

        if (valid) {
            size_t base = (size_t)row * HID + c;
            float2 m = *reinterpret_cast<float2*>(mem + base);
            float2 sv = *reinterpret_cast<float2*>(spksum + base);
            float v0 = m.x + lo32(acc);
            float v1 = m.y + hi32(acc);
            bool s0 = (v0 >= 1.0f);
            bool s1 = (v1 >= 1.0f);
            m.x = s0 ? 0.0f : v0;
            m.y = s1 ? 0.0f : v1;
            if (s0) sv.x += 1.0f;
            if (s1) sv.y += 1.0f;
            *reinterpret_cast<float2*>(mem + base) = m;
            *reinterpret_cast<float2*>(spksum + base) = sv;
        }
    }
}

// Dense fused C = A(8192 x K) @ W(N x K)^T ; then LIF update.
// Tiles 128x128x16, 256 threads, 8x8 per thread; packed f32x2 FMAs.
// Per-thread cols {tx*4..+3} u {64+tx*4..+3}: conflict-free B LDS.128.
__global__ __launch_bounds__(256, 1) void gemm_lif_kernel(
    const float* __restrict__ A, const float* __restrict__ W,
    float* __restrict__ mem, float* __restrict__ spksum,
    int N, int K)
{
    __shared__ float As[16][132];
    __shared__ float Bs[16][132];

    const int tid  = threadIdx.x;
    const int row0 = blockIdx.y * 128;
    const int col0 = blockIdx.x * 128;
    const int lr = tid >> 2;          // 0..63
    const int lk = (tid & 3) << 2;    // 0,4,8,12
    const int ty = tid >> 4;          // 0..15
    const int tx = tid & 15;          // 0..15

    unsigned long long acc2[8][4];
#pragma unroll
    for (int i = 0; i < 8; i++)
#pragma unroll
        for (int j = 0; j < 4; j++) acc2[i][j] = 0ull;

    for (int k0 = 0; k0 < K; k0 += 16) {
#pragma unroll
        for (int h = 0; h < 2; h++) {
            int r = lr + (h << 6);
            float4 va = *reinterpret_cast<const float4*>(
                A + (size_t)(row0 + r) * K + (k0 + lk));
            As[lk + 0][r] = va.x; As[lk + 1][r] = va.y;
            As[lk + 2][r] = va.z; As[lk + 3][r] = va.w;
            int gn = col0 + r;
            float4 vb = make_float4(0.f, 0.f, 0.f, 0.f);
            if (gn < N)
                vb = *reinterpret_cast<const float4*>(
                    W + (size_t)gn * K + (k0 + lk));
            Bs[lk + 0][r] = vb.x; Bs[lk + 1][r] = vb.y;
            Bs[lk + 2][r] = vb.z; Bs[lk + 3][r] = vb.w;
        }
        __syncthreads();
#pragma unroll
        for (int kk = 0; kk < 16; kk++) {
            float a[8];
            *reinterpret_cast<float4*>(&a[0]) =
                *reinterpret_cast<const float4*>(&As[kk][ty * 8]);
            *reinterpret_cast<float4*>(&a[4]) =
                *reinterpret_cast<const float4*>(&As[kk][ty * 8 + 4]);
            ulonglong2 b01 = *reinterpret_cast<const ulonglong2*>(&Bs[kk][tx * 4]);
            ulonglong2 b23 = *reinterpret_cast<const ulonglong2*>(&Bs[kk][64 + tx * 4]);
#pragma unroll
            for (int i = 0; i < 8; i++) {
                unsigned long long a2 = bcast2(a[i]);
                fma2(acc2[i][0], a2, b01.x);
                fma2(acc2[i][1], a2, b01.y);
                fma2(acc2[i][2], a2, b23.x);
                fma2(acc2[i][3], a2, b23.y);
            }
        }
        __syncthreads();
    }

    // LIF epilogue: mem += impulse; spike = mem >= 1; reset; sum += spike
#pragma unroll
    for (int i = 0; i < 8; i++) {
        int r = row0 + ty * 8 + i;
#pragma unroll
        for (int hb = 0; hb < 2; hb++) {
            int cbase = col0 + hb * 64 + tx * 4;
            if (cbase < N) {
                float av[4] = { lo32(acc2[i][2 * hb]),     hi32(acc2[i][2 * hb]),
                                lo32(acc2[i][2 * hb + 1]), hi32(acc2[i][2 * hb + 1]) };
                size_t idx = (size_t)r * N + cbase;
                float4 m = *reinterpret_cast<float4*>(mem + idx);
                float4 sv = *reinterpret_cast<float4*>(spksum + idx);
                float* mp = &m.x; float* sp = &sv.x;
#pragma unroll
                for (int e = 0; e < 4; e++) {
                    float v = mp[e] + av[e];
                    bool s = (v >= 1.0f);
                    mp[e] = s ? 0.0f : v;
                    if (s) sp[e] += 1.0f;
                }
                *reinterpret_cast<float4*>(mem + idx) = m;
                *reinterpret_cast<float4*>(spksum + idx) = sv;
            }
        }
    }
}

// Layer 3: one warp per batch row, W3 (10 x 1200) cached in SMEM.
__global__ __launch_bounds__(256) void layer3_kernel(
    const float* __restrict__ A /* g_sum2 */, const float* __restrict__ W3,
    float* __restrict__ out, int last)
{
    __shared__ float W3s[DOUT * HID];
    for (int i = threadIdx.x; i < DOUT * HID; i += blockDim.x)
        W3s[i] = W3[i];
    __syncthreads();

    int warp = (blockIdx.x * blockDim.x + threadIdx.x) >> 5;
    int lane = threadIdx.x & 31;
    if (warp >= BATCH) return;

    const float* a = A + (size_t)warp * HID;
    float acc[DOUT];
#pragma unroll
    for (int n = 0; n < DOUT; n++) acc[n] = 0.f;

    for (int k = lane; k < HID; k += 32) {
        float av = a[k];
#pragma unroll
        for (int n = 0; n < DOUT; n++)
            acc[n] = fmaf(av, W3s[n * HID + k], acc[n]);
    }
#pragma unroll
    for (int n = 0; n < DOUT; n++) {
#pragma unroll
        for (int off = 16; off; off >>= 1)
            acc[n] += __shfl_xor_sync(0xffffffffu, acc[n], off);
    }
    if (lane < DOUT) {
        size_t idx = (size_t)warp * DOUT + lane;
        float m = g_mem3[idx] + acc[lane];
        bool s = (m >= 1.0f);
        g_mem3[idx] = s ? 0.0f : m;
        float s3 = g_sum3[idx] + (s ? 1.0f : 0.0f);
        g_sum3[idx] = s3;
        if (last) out[idx] = s3 / 35.0f;   // match reference: exact fp32 divide
    }
}

// ---------------- host ----------------
extern "C" void kernel_launch(void* const* d_in, const int* in_sizes, int n_in,
                              void* d_out, int out_size)
{
    const float* x  = (const float*)d_in[0];
    const float* W1 = (const float*)d_in[1];
    const float* W2 = (const float*)d_in[2];
    const float* W3 = (const float*)d_in[3];
    float* out = (float*)d_out;

    float *mem1, *sum1, *mem2, *sum2;
    cudaGetSymbolAddress((void**)&mem1, g_mem1);
    cudaGetSymbolAddress((void**)&sum1, g_sum1);
    cudaGetSymbolAddress((void**)&mem2, g_mem2);
    cudaGetSymbolAddress((void**)&sum2, g_sum2);

    const int l1_smem = DIN * NC1 * sizeof(float);   // 200704 B
    cudaFuncSetAttribute(layer1_sparse_kernel,
                         cudaFuncAttributeMaxDynamicSharedMemorySize, l1_smem);

    zero_state_kernel<<<512, 256>>>();
    transpose_w1_kernel<<<(DIN * HID + 255) / 256, 256>>>(W1);

    const dim3 l1_grid(BATCH / 512, (HID + NC1 - 1) / NC1);  // (16, 19)
    const dim3 gemm_grid((HID + 127) / 128, BATCH / 128);    // (10, 64)

    for (int t = 0; t < TSTEPS; t++) {
        // kt = fold_in(key(42), t) = threefry2x32((0,42), (0,t))
        uint32_t kt0, kt1;
        threefry2x32(0u, 42u, 0u, (uint32_t)t, kt0, kt1);

        spike_compact_kernel<<<BATCH / 8, 256>>>(x, kt0, kt1);
        layer1_sparse_kernel<<<l1_grid, 512, l1_smem>>>(mem1, sum1);
        gemm_lif_kernel<<<gemm_grid, 256>>>(sum1, W2, mem2, sum2, HID, HID);
        layer3_kernel<<<BATCH / 8, 256>>>(sum2, W3, out, (t == TSTEPS - 1) ? 1 : 0);
    }
}